// round 1
// baseline (speedup 1.0000x reference)
#include <cuda_runtime.h>
#include <math.h>

#define BSZ 4
#define SSZ 2048
#define ESZ 1024
#define HSZ 16
#define DSZ 64

// Scratch (allocation-free): Q/K/V laid out [B][H][S][D]; attn out [B][S][H][D]
__device__ float g_q[BSZ*HSZ*SSZ*DSZ];
__device__ float g_k[BSZ*HSZ*SSZ*DSZ];
__device__ float g_v[BSZ*HSZ*SSZ*DSZ];
__device__ float g_attn[BSZ*SSZ*HSZ*DSZ];

// ---------------------------------------------------------------------------
// Tiled SGEMM: C = A[M,K=1024] * B[K,N] + bias
// mode 0: N=3072, scatter into g_q/g_k/g_v with q-scale (QKV projection)
// mode 1: N=1024, A := g_attn, plain write to out (output projection)
// BM=BN=128, BK=8, 256 threads, 8x8 per-thread microtile.
// ---------------------------------------------------------------------------
__global__ __launch_bounds__(256) void gemm_kernel(
    const float* __restrict__ A, const float* __restrict__ Bm,
    const float* __restrict__ bias, float* __restrict__ out,
    const int* __restrict__ lidx, int N, int mode)
{
    const int K = 1024;
    __shared__ float As[8][128];   // transposed A tile
    __shared__ float Bs[8][128];

    const float* Ap = (mode == 1) ? (const float*)g_attn : A;

    int tid = threadIdx.x;
    int bm = blockIdx.y;
    int bn = blockIdx.x;

    const float* Ab = Ap + (size_t)bm * 128 * K;
    const float* Bb = Bm + (size_t)bn * 128;

    int aRow  = tid >> 1;          // 0..127
    int aCol4 = (tid & 1) * 4;     // 0 or 4
    int bRow  = tid >> 5;          // 0..7
    int bCol4 = (tid & 31) * 4;    // 0..124

    int tr = (tid >> 4) * 8;       // thread row base in tile
    int tc = (tid & 15) * 8;       // thread col base in tile

    float acc[8][8];
    #pragma unroll
    for (int i = 0; i < 8; i++)
        #pragma unroll
        for (int j = 0; j < 8; j++) acc[i][j] = 0.f;

    for (int k0 = 0; k0 < K; k0 += 8) {
        float4 a4 = *(const float4*)(Ab + (size_t)aRow * K + k0 + aCol4);
        As[aCol4 + 0][aRow] = a4.x;
        As[aCol4 + 1][aRow] = a4.y;
        As[aCol4 + 2][aRow] = a4.z;
        As[aCol4 + 3][aRow] = a4.w;
        float4 b4 = *(const float4*)(Bb + (size_t)(k0 + bRow) * N + bCol4);
        *(float4*)&Bs[bRow][bCol4] = b4;
        __syncthreads();

        #pragma unroll
        for (int kk = 0; kk < 8; kk++) {
            float regM[8], regN[8];
            #pragma unroll
            for (int i = 0; i < 8; i++) regM[i] = As[kk][tr + i];
            #pragma unroll
            for (int j = 0; j < 8; j++) regN[j] = Bs[kk][tc + j];
            #pragma unroll
            for (int i = 0; i < 8; i++)
                #pragma unroll
                for (int j = 0; j < 8; j++)
                    acc[i][j] = fmaf(regM[i], regN[j], acc[i][j]);
        }
        __syncthreads();
    }

    if (mode == 0) {
        // scale = rsqrt(D) / (layer_idx + 1); read low 32 bits (works for i32/i64)
        float scale = 0.125f / (float)(lidx[0] + 1);
        #pragma unroll
        for (int i = 0; i < 8; i++) {
            int m = bm * 128 + tr + i;
            int b = m >> 11;           // / 2048
            int s = m & 2047;
            #pragma unroll
            for (int j = 0; j < 8; j++) {
                int n = bn * 128 + tc + j;
                float v = acc[i][j] + bias[n];
                int t  = n >> 10;      // 0=q,1=k,2=v
                int hd = n & 1023;
                int h = hd >> 6, d = hd & 63;
                size_t idx = ((size_t)(b * HSZ + h) * SSZ + s) * DSZ + d;
                if (t == 0)      g_q[idx] = v * scale;
                else if (t == 1) g_k[idx] = v;
                else             g_v[idx] = v;
            }
        }
    } else {
        #pragma unroll
        for (int i = 0; i < 8; i++) {
            int m = bm * 128 + tr + i;
            #pragma unroll
            for (int j = 0; j < 8; j++) {
                int n = bn * 128 + tc + j;
                out[(size_t)m * N + n] = acc[i][j] + bias[n];
            }
        }
    }
}

// ---------------------------------------------------------------------------
// Flash-style causal attention. One block = 64 query rows of one (b,h).
// 256 threads = 8 warps; warp owns 8 query rows; lane owns key/out cols
// {lane, lane+32}. Online softmax; P staged through smem for conflict-free PV.
// ---------------------------------------------------------------------------
__global__ __launch_bounds__(256) void attn_kernel()
{
    extern __shared__ float sm[];
    float (*Qs)[64] = (float(*)[64])(sm);              // 4096 floats
    float (*Ks)[65] = (float(*)[65])(sm + 4096);       // 4160 floats (padded)
    float (*Vs)[64] = (float(*)[64])(sm + 4096 + 4160);// 4096 floats
    float (*Ps)[64] = (float(*)[64])(sm + 4096 + 4160 + 4096); // 4096 floats

    int bh = blockIdx.y;
    int qb = blockIdx.x;            // query tile index
    int q0 = qb * 64;

    const float* qp = g_q + (size_t)bh * SSZ * DSZ + (size_t)q0 * DSZ;
    const float* kb = g_k + (size_t)bh * SSZ * DSZ;
    const float* vb = g_v + (size_t)bh * SSZ * DSZ;

    int tid = threadIdx.x, lane = tid & 31, warp = tid >> 5;
    int r0 = warp * 8;

    // Load Q tile (64x64 floats = 1024 float4)
    for (int i = tid; i < 1024; i += 256)
        ((float4*)Qs)[i] = ((const float4*)qp)[i];

    float m_i[8], l_i[8], o0[8], o1[8];
    #pragma unroll
    for (int r = 0; r < 8; r++) { m_i[r] = -1e30f; l_i[r] = 0.f; o0[r] = 0.f; o1[r] = 0.f; }

    int ntiles = qb + 1;            // causal: only key tiles <= query tile
    for (int kt = 0; kt < ntiles; kt++) {
        __syncthreads();
        const float* kp = kb + (size_t)kt * 64 * DSZ;
        const float* vp = vb + (size_t)kt * 64 * DSZ;
        for (int i = tid; i < 1024; i += 256) {
            float4 k4 = ((const float4*)kp)[i];
            int row = i >> 4, c = (i & 15) * 4;
            Ks[row][c + 0] = k4.x; Ks[row][c + 1] = k4.y;
            Ks[row][c + 2] = k4.z; Ks[row][c + 3] = k4.w;
            ((float4*)Vs)[i] = ((const float4*)vp)[i];
        }
        __syncthreads();

        // Scores: lane computes s[r] vs keys (lane) and (lane+32)
        float s0[8], s1[8];
        #pragma unroll
        for (int r = 0; r < 8; r++) { s0[r] = 0.f; s1[r] = 0.f; }

        #pragma unroll 4
        for (int d = 0; d < 64; d += 4) {
            float ka0 = Ks[lane][d],      ka1 = Ks[lane][d+1];
            float ka2 = Ks[lane][d+2],    ka3 = Ks[lane][d+3];
            float kb0 = Ks[lane+32][d],   kb1 = Ks[lane+32][d+1];
            float kb2 = Ks[lane+32][d+2], kb3 = Ks[lane+32][d+3];
            #pragma unroll
            for (int r = 0; r < 8; r++) {
                float4 q4 = *(const float4*)&Qs[r0 + r][d];
                s0[r] = fmaf(q4.x, ka0, s0[r]); s0[r] = fmaf(q4.y, ka1, s0[r]);
                s0[r] = fmaf(q4.z, ka2, s0[r]); s0[r] = fmaf(q4.w, ka3, s0[r]);
                s1[r] = fmaf(q4.x, kb0, s1[r]); s1[r] = fmaf(q4.y, kb1, s1[r]);
                s1[r] = fmaf(q4.z, kb2, s1[r]); s1[r] = fmaf(q4.w, kb3, s1[r]);
            }
        }

        bool lastTile = (kt == qb);   // diagonal tile needs masking
        #pragma unroll
        for (int r = 0; r < 8; r++) {
            float a0 = s0[r], a1 = s1[r];
            if (lastTile) {
                int qrel = r0 + r;
                if (lane      > qrel) a0 = -1e30f;
                if (lane + 32 > qrel) a1 = -1e30f;
            }
            float mx = fmaxf(a0, a1);
            #pragma unroll
            for (int off = 16; off; off >>= 1)
                mx = fmaxf(mx, __shfl_xor_sync(0xffffffffu, mx, off));
            float mnew = fmaxf(m_i[r], mx);
            float p0 = __expf(a0 - mnew);
            float p1 = __expf(a1 - mnew);
            float ps = p0 + p1;
            #pragma unroll
            for (int off = 16; off; off >>= 1)
                ps += __shfl_xor_sync(0xffffffffu, ps, off);
            float alpha = __expf(m_i[r] - mnew);
            l_i[r] = l_i[r] * alpha + ps;
            m_i[r] = mnew;
            o0[r] *= alpha;
            o1[r] *= alpha;
            Ps[r0 + r][lane]      = p0;
            Ps[r0 + r][lane + 32] = p1;
        }
        __syncwarp();

        // PV: O[r][c] += sum_j P[r][j] * V[j][c], c in {lane, lane+32}
        #pragma unroll 4
        for (int j = 0; j < 64; j += 4) {
            float va0 = Vs[j][lane],      va1 = Vs[j+1][lane];
            float va2 = Vs[j+2][lane],    va3 = Vs[j+3][lane];
            float vb0 = Vs[j][lane+32],   vb1 = Vs[j+1][lane+32];
            float vb2 = Vs[j+2][lane+32], vb3 = Vs[j+3][lane+32];
            #pragma unroll
            for (int r = 0; r < 8; r++) {
                float4 p4 = *(const float4*)&Ps[r0 + r][j];
                o0[r] = fmaf(p4.x, va0, o0[r]); o0[r] = fmaf(p4.y, va1, o0[r]);
                o0[r] = fmaf(p4.z, va2, o0[r]); o0[r] = fmaf(p4.w, va3, o0[r]);
                o1[r] = fmaf(p4.x, vb0, o1[r]); o1[r] = fmaf(p4.y, vb1, o1[r]);
                o1[r] = fmaf(p4.z, vb2, o1[r]); o1[r] = fmaf(p4.w, vb3, o1[r]);
            }
        }
        __syncwarp();
    }

    // Epilogue: normalize and write [B][S][H][D]
    int b = bh >> 4, h = bh & 15;
    #pragma unroll
    for (int r = 0; r < 8; r++) {
        int s = q0 + r0 + r;
        float inv = 1.f / l_i[r];
        size_t base = ((size_t)(b * SSZ + s) * HSZ + h) * DSZ;
        g_attn[base + lane]      = o0[r] * inv;
        g_attn[base + lane + 32] = o1[r] * inv;
    }
}

extern "C" void kernel_launch(void* const* d_in, const int* in_sizes, int n_in,
                              void* d_out, int out_size)
{
    const float* hidden = (const float*)d_in[0];
    // d_in[1] = mask (tril) — causality handled analytically
    const float* Wqkv  = (const float*)d_in[2];
    const float* bqkv  = (const float*)d_in[3];
    const float* Wproj = (const float*)d_in[4];
    const float* bproj = (const float*)d_in[5];
    const int*   lidx  = (const int*)d_in[6];
    float* out = (float*)d_out;

    cudaFuncSetAttribute(attn_kernel,
        cudaFuncAttributeMaxDynamicSharedMemorySize, 65792);

    // QKV projection: M=8192, N=3072, K=1024
    gemm_kernel<<<dim3(24, 64), 256>>>(hidden, Wqkv, bqkv, nullptr, lidx, 3072, 0);
    // Attention: 32 query tiles x 64 (b,h) pairs
    attn_kernel<<<dim3(32, 64), 256, 65792>>>();
    // Output projection: M=8192, N=1024, K=1024 (A := g_attn inside kernel)
    gemm_kernel<<<dim3(8, 64), 256>>>(nullptr, Wproj, bproj, out, lidx, 1024, 1);
}

// round 2
// speedup vs baseline: 1.2069x; 1.2069x over previous
#include <cuda_runtime.h>
#include <math.h>
#include <stdint.h>

#define BSZ 4
#define SSZ 2048
#define ESZ 1024
#define HSZ 16
#define DSZ 64

// Scratch (allocation-free): Q/K/V laid out [B][H][S][D]; attn out [B][S][H][D]
__device__ float g_q[BSZ*HSZ*SSZ*DSZ];
__device__ float g_k[BSZ*HSZ*SSZ*DSZ];
__device__ float g_v[BSZ*HSZ*SSZ*DSZ];
__device__ float g_attn[BSZ*SSZ*HSZ*DSZ];

__device__ __forceinline__ uint32_t f2tf32(float x) {
    uint32_t r;
    asm("cvt.rna.tf32.f32 %0, %1;" : "=r"(r) : "f"(x));
    return r;
}

__device__ __forceinline__ void mma_tf32(float& d0, float& d1, float& d2, float& d3,
                                         uint32_t a0, uint32_t a1, uint32_t a2, uint32_t a3,
                                         uint32_t b0, uint32_t b1) {
    asm volatile(
        "mma.sync.aligned.m16n8k8.row.col.f32.tf32.tf32.f32 "
        "{%0,%1,%2,%3},{%4,%5,%6,%7},{%8,%9},{%0,%1,%2,%3};"
        : "+f"(d0), "+f"(d1), "+f"(d2), "+f"(d3)
        : "r"(a0), "r"(a1), "r"(a2), "r"(a3), "r"(b0), "r"(b1));
}

// ---------------------------------------------------------------------------
// Tensor-core SGEMM via 3xTF32: C = A[M,1024] * B[1024,N] + bias
// mode 0: N=3072, scatter into g_q/g_k/g_v with q-scale (QKV projection)
// mode 1: N=1024, A := g_attn, plain write to out (output projection)
// BM=BN=128, BK=32, 256 threads (8 warps, warp tile 64x32).
// ---------------------------------------------------------------------------
__global__ __launch_bounds__(256) void gemm_tc_kernel(
    const float* __restrict__ A, const float* __restrict__ Bm,
    const float* __restrict__ bias, float* __restrict__ out,
    const int* __restrict__ lidx, int N, int mode)
{
    const int K = 1024;
    __shared__ float As[128][36];   // [m][k], padded: conflict-free frag loads
    __shared__ float Bs[32][136];   // [k][n], padded: conflict-free frag loads

    const float* Ap = (mode == 1) ? (const float*)g_attn : A;

    int tid = threadIdx.x;
    int bm = blockIdx.y;
    int bn = blockIdx.x;
    int lane = tid & 31, warp = tid >> 5;
    int wm = (warp >> 2) * 64;      // warp tile origin in block
    int wn = (warp & 3) * 32;
    int r = lane >> 2;              // 0..7
    int c = lane & 3;               // 0..3

    const float* Ab = Ap + (size_t)bm * 128 * K;
    const float* Bb = Bm + (size_t)bn * 128;

    // gmem load assignment
    int aM = tid >> 1;              // 0..127
    int aK = (tid & 1) * 16;        // 0 or 16 (covers 16 floats)
    int bK = tid >> 3;              // 0..31
    int bN = (tid & 7) * 16;        // 0..112

    float acc[4][4][4];             // [mi][ni][e]
    #pragma unroll
    for (int mi = 0; mi < 4; mi++)
        #pragma unroll
        for (int ni = 0; ni < 4; ni++)
            #pragma unroll
            for (int e = 0; e < 4; e++) acc[mi][ni][e] = 0.f;

    // prefetch first tile into registers
    float4 aPref[4], bPref[4];
    #pragma unroll
    for (int j = 0; j < 4; j++) {
        aPref[j] = *(const float4*)(Ab + (size_t)aM * K + aK + j * 4);
        bPref[j] = *(const float4*)(Bb + (size_t)bK * N + bN + j * 4);
    }

    for (int k0 = 0; k0 < K; k0 += 32) {
        // commit prefetched tile to smem
        #pragma unroll
        for (int j = 0; j < 4; j++) {
            *(float4*)&As[aM][aK + j * 4] = aPref[j];
            *(float4*)&Bs[bK][bN + j * 4] = bPref[j];
        }
        __syncthreads();

        // prefetch next tile (overlaps with mma work below)
        if (k0 + 32 < K) {
            #pragma unroll
            for (int j = 0; j < 4; j++) {
                aPref[j] = *(const float4*)(Ab + (size_t)aM * K + k0 + 32 + aK + j * 4);
                bPref[j] = *(const float4*)(Bb + (size_t)(k0 + 32 + bK) * N + bN + j * 4);
            }
        }

        #pragma unroll
        for (int ks = 0; ks < 4; ks++) {
            int k8 = ks * 8;
            // load + split A fragments (4 m-frags x 4 elems)
            uint32_t abig[4][4], asml[4][4];
            #pragma unroll
            for (int mi = 0; mi < 4; mi++) {
                int mrow = wm + mi * 16 + r;
                float a0 = As[mrow][k8 + c];
                float a1 = As[mrow + 8][k8 + c];
                float a2 = As[mrow][k8 + c + 4];
                float a3 = As[mrow + 8][k8 + c + 4];
                abig[mi][0] = f2tf32(a0); asml[mi][0] = f2tf32(a0 - __uint_as_float(abig[mi][0]));
                abig[mi][1] = f2tf32(a1); asml[mi][1] = f2tf32(a1 - __uint_as_float(abig[mi][1]));
                abig[mi][2] = f2tf32(a2); asml[mi][2] = f2tf32(a2 - __uint_as_float(abig[mi][2]));
                abig[mi][3] = f2tf32(a3); asml[mi][3] = f2tf32(a3 - __uint_as_float(abig[mi][3]));
            }
            // load + split B fragments (4 n-frags x 2 elems)
            uint32_t bbig[4][2], bsml[4][2];
            #pragma unroll
            for (int ni = 0; ni < 4; ni++) {
                int ncol = wn + ni * 8 + r;
                float b0 = Bs[k8 + c][ncol];
                float b1 = Bs[k8 + c + 4][ncol];
                bbig[ni][0] = f2tf32(b0); bsml[ni][0] = f2tf32(b0 - __uint_as_float(bbig[ni][0]));
                bbig[ni][1] = f2tf32(b1); bsml[ni][1] = f2tf32(b1 - __uint_as_float(bbig[ni][1]));
            }
            // 3xTF32: Ab*Bb + Ab*Bs + As*Bb
            #pragma unroll
            for (int mi = 0; mi < 4; mi++)
                #pragma unroll
                for (int ni = 0; ni < 4; ni++) {
                    float* d = acc[mi][ni];
                    mma_tf32(d[0], d[1], d[2], d[3],
                             abig[mi][0], abig[mi][1], abig[mi][2], abig[mi][3],
                             bbig[ni][0], bbig[ni][1]);
                    mma_tf32(d[0], d[1], d[2], d[3],
                             abig[mi][0], abig[mi][1], abig[mi][2], abig[mi][3],
                             bsml[ni][0], bsml[ni][1]);
                    mma_tf32(d[0], d[1], d[2], d[3],
                             asml[mi][0], asml[mi][1], asml[mi][2], asml[mi][3],
                             bbig[ni][0], bbig[ni][1]);
                }
        }
        __syncthreads();
    }

    // Epilogue. acc elem e: row = r + (e>>1)*8, col = c*2 + (e&1)
    if (mode == 0) {
        float scale = 0.125f / (float)(lidx[0] + 1);
        #pragma unroll
        for (int mi = 0; mi < 4; mi++) {
            #pragma unroll
            for (int ni = 0; ni < 4; ni++) {
                #pragma unroll
                for (int e = 0; e < 4; e++) {
                    int m = bm * 128 + wm + mi * 16 + r + (e >> 1) * 8;
                    int n = bn * 128 + wn + ni * 8 + c * 2 + (e & 1);
                    float v = acc[mi][ni][e] + bias[n];
                    int b = m >> 11, s = m & 2047;
                    int t = n >> 10;
                    int hd = n & 1023;
                    int h = hd >> 6, d = hd & 63;
                    size_t idx = ((size_t)(b * HSZ + h) * SSZ + s) * DSZ + d;
                    if (t == 0)      g_q[idx] = v * scale;
                    else if (t == 1) g_k[idx] = v;
                    else             g_v[idx] = v;
                }
            }
        }
    } else {
        #pragma unroll
        for (int mi = 0; mi < 4; mi++) {
            #pragma unroll
            for (int ni = 0; ni < 4; ni++) {
                #pragma unroll
                for (int e = 0; e < 4; e++) {
                    int m = bm * 128 + wm + mi * 16 + r + (e >> 1) * 8;
                    int n = bn * 128 + wn + ni * 8 + c * 2 + (e & 1);
                    out[(size_t)m * N + n] = acc[mi][ni][e] + bias[n];
                }
            }
        }
    }
}

// ---------------------------------------------------------------------------
// Flash-style causal attention (unchanged from R1). One block = 64 query rows
// of one (b,h). 256 threads; warp owns 8 query rows; lane owns cols {lane,lane+32}.
// ---------------------------------------------------------------------------
__global__ __launch_bounds__(256) void attn_kernel()
{
    extern __shared__ float sm[];
    float (*Qs)[64] = (float(*)[64])(sm);
    float (*Ks)[65] = (float(*)[65])(sm + 4096);
    float (*Vs)[64] = (float(*)[64])(sm + 4096 + 4160);
    float (*Ps)[64] = (float(*)[64])(sm + 4096 + 4160 + 4096);

    int bh = blockIdx.y;
    int qb = blockIdx.x;
    int q0 = qb * 64;

    const float* qp = g_q + (size_t)bh * SSZ * DSZ + (size_t)q0 * DSZ;
    const float* kb = g_k + (size_t)bh * SSZ * DSZ;
    const float* vb = g_v + (size_t)bh * SSZ * DSZ;

    int tid = threadIdx.x, lane = tid & 31, warp = tid >> 5;
    int r0 = warp * 8;

    for (int i = tid; i < 1024; i += 256)
        ((float4*)Qs)[i] = ((const float4*)qp)[i];

    float m_i[8], l_i[8], o0[8], o1[8];
    #pragma unroll
    for (int r = 0; r < 8; r++) { m_i[r] = -1e30f; l_i[r] = 0.f; o0[r] = 0.f; o1[r] = 0.f; }

    int ntiles = qb + 1;
    for (int kt = 0; kt < ntiles; kt++) {
        __syncthreads();
        const float* kp = kb + (size_t)kt * 64 * DSZ;
        const float* vp = vb + (size_t)kt * 64 * DSZ;
        for (int i = tid; i < 1024; i += 256) {
            float4 k4 = ((const float4*)kp)[i];
            int row = i >> 4, cc = (i & 15) * 4;
            Ks[row][cc + 0] = k4.x; Ks[row][cc + 1] = k4.y;
            Ks[row][cc + 2] = k4.z; Ks[row][cc + 3] = k4.w;
            ((float4*)Vs)[i] = ((const float4*)vp)[i];
        }
        __syncthreads();

        float s0[8], s1[8];
        #pragma unroll
        for (int r = 0; r < 8; r++) { s0[r] = 0.f; s1[r] = 0.f; }

        #pragma unroll 4
        for (int d = 0; d < 64; d += 4) {
            float ka0 = Ks[lane][d],      ka1 = Ks[lane][d+1];
            float ka2 = Ks[lane][d+2],    ka3 = Ks[lane][d+3];
            float kb0 = Ks[lane+32][d],   kb1 = Ks[lane+32][d+1];
            float kb2 = Ks[lane+32][d+2], kb3 = Ks[lane+32][d+3];
            #pragma unroll
            for (int r = 0; r < 8; r++) {
                float4 q4 = *(const float4*)&Qs[r0 + r][d];
                s0[r] = fmaf(q4.x, ka0, s0[r]); s0[r] = fmaf(q4.y, ka1, s0[r]);
                s0[r] = fmaf(q4.z, ka2, s0[r]); s0[r] = fmaf(q4.w, ka3, s0[r]);
                s1[r] = fmaf(q4.x, kb0, s1[r]); s1[r] = fmaf(q4.y, kb1, s1[r]);
                s1[r] = fmaf(q4.z, kb2, s1[r]); s1[r] = fmaf(q4.w, kb3, s1[r]);
            }
        }

        bool lastTile = (kt == qb);
        #pragma unroll
        for (int r = 0; r < 8; r++) {
            float a0 = s0[r], a1 = s1[r];
            if (lastTile) {
                int qrel = r0 + r;
                if (lane      > qrel) a0 = -1e30f;
                if (lane + 32 > qrel) a1 = -1e30f;
            }
            float mx = fmaxf(a0, a1);
            #pragma unroll
            for (int off = 16; off; off >>= 1)
                mx = fmaxf(mx, __shfl_xor_sync(0xffffffffu, mx, off));
            float mnew = fmaxf(m_i[r], mx);
            float p0 = __expf(a0 - mnew);
            float p1 = __expf(a1 - mnew);
            float ps = p0 + p1;
            #pragma unroll
            for (int off = 16; off; off >>= 1)
                ps += __shfl_xor_sync(0xffffffffu, ps, off);
            float alpha = __expf(m_i[r] - mnew);
            l_i[r] = l_i[r] * alpha + ps;
            m_i[r] = mnew;
            o0[r] *= alpha;
            o1[r] *= alpha;
            Ps[r0 + r][lane]      = p0;
            Ps[r0 + r][lane + 32] = p1;
        }
        __syncwarp();

        #pragma unroll 4
        for (int j = 0; j < 64; j += 4) {
            float va0 = Vs[j][lane],      va1 = Vs[j+1][lane];
            float va2 = Vs[j+2][lane],    va3 = Vs[j+3][lane];
            float vb0 = Vs[j][lane+32],   vb1 = Vs[j+1][lane+32];
            float vb2 = Vs[j+2][lane+32], vb3 = Vs[j+3][lane+32];
            #pragma unroll
            for (int r = 0; r < 8; r++) {
                float4 p4 = *(const float4*)&Ps[r0 + r][j];
                o0[r] = fmaf(p4.x, va0, o0[r]); o0[r] = fmaf(p4.y, va1, o0[r]);
                o0[r] = fmaf(p4.z, va2, o0[r]); o0[r] = fmaf(p4.w, va3, o0[r]);
                o1[r] = fmaf(p4.x, vb0, o1[r]); o1[r] = fmaf(p4.y, vb1, o1[r]);
                o1[r] = fmaf(p4.z, vb2, o1[r]); o1[r] = fmaf(p4.w, vb3, o1[r]);
            }
        }
        __syncwarp();
    }

    int b = bh >> 4, h = bh & 15;
    #pragma unroll
    for (int r = 0; r < 8; r++) {
        int s = q0 + r0 + r;
        float inv = 1.f / l_i[r];
        size_t base = ((size_t)(b * SSZ + s) * HSZ + h) * DSZ;
        g_attn[base + lane]      = o0[r] * inv;
        g_attn[base + lane + 32] = o1[r] * inv;
    }
}

extern "C" void kernel_launch(void* const* d_in, const int* in_sizes, int n_in,
                              void* d_out, int out_size)
{
    const float* hidden = (const float*)d_in[0];
    const float* Wqkv  = (const float*)d_in[2];
    const float* bqkv  = (const float*)d_in[3];
    const float* Wproj = (const float*)d_in[4];
    const float* bproj = (const float*)d_in[5];
    const int*   lidx  = (const int*)d_in[6];
    float* out = (float*)d_out;

    cudaFuncSetAttribute(attn_kernel,
        cudaFuncAttributeMaxDynamicSharedMemorySize, 65792);

    // QKV projection: M=8192, N=3072, K=1024
    gemm_tc_kernel<<<dim3(24, 64), 256>>>(hidden, Wqkv, bqkv, nullptr, lidx, 3072, 0);
    // Attention: 32 query tiles x 64 (b,h) pairs
    attn_kernel<<<dim3(32, 64), 256, 65792>>>();
    // Output projection: M=8192, N=1024, K=1024 (A := g_attn inside kernel)
    gemm_tc_kernel<<<dim3(8, 64), 256>>>(nullptr, Wproj, bproj, out, lidx, 1024, 1);
}

// round 3
// speedup vs baseline: 1.4140x; 1.1716x over previous
#include <cuda_runtime.h>
#include <math.h>
#include <stdint.h>

#define BSZ 4
#define SSZ 2048
#define ESZ 1024
#define HSZ 16
#define DSZ 64

#define APAD 68   // pad for Q/K/P smem rows (conflict-free frag reads)
#define VPAD 72   // pad for V smem rows (conflict-free B-frag reads)

// Scratch (allocation-free): Q/K/V laid out [B][H][S][D]; attn out [B][S][H][D]
__device__ float g_q[BSZ*HSZ*SSZ*DSZ];
__device__ float g_k[BSZ*HSZ*SSZ*DSZ];
__device__ float g_v[BSZ*HSZ*SSZ*DSZ];
__device__ float g_attn[BSZ*SSZ*HSZ*DSZ];

__device__ __forceinline__ uint32_t f2tf32(float x) {
    uint32_t r;
    asm("cvt.rna.tf32.f32 %0, %1;" : "=r"(r) : "f"(x));
    return r;
}

__device__ __forceinline__ void mma_tf32(float& d0, float& d1, float& d2, float& d3,
                                         uint32_t a0, uint32_t a1, uint32_t a2, uint32_t a3,
                                         uint32_t b0, uint32_t b1) {
    asm volatile(
        "mma.sync.aligned.m16n8k8.row.col.f32.tf32.tf32.f32 "
        "{%0,%1,%2,%3},{%4,%5,%6,%7},{%8,%9},{%0,%1,%2,%3};"
        : "+f"(d0), "+f"(d1), "+f"(d2), "+f"(d3)
        : "r"(a0), "r"(a1), "r"(a2), "r"(a3), "r"(b0), "r"(b1));
}

// ---------------------------------------------------------------------------
// Tensor-core SGEMM via 3xTF32 (unchanged from R2)
// ---------------------------------------------------------------------------
__global__ __launch_bounds__(256) void gemm_tc_kernel(
    const float* __restrict__ A, const float* __restrict__ Bm,
    const float* __restrict__ bias, float* __restrict__ out,
    const int* __restrict__ lidx, int N, int mode)
{
    const int K = 1024;
    __shared__ float As[128][36];
    __shared__ float Bs[32][136];

    const float* Ap = (mode == 1) ? (const float*)g_attn : A;

    int tid = threadIdx.x;
    int bm = blockIdx.y;
    int bn = blockIdx.x;
    int lane = tid & 31, warp = tid >> 5;
    int wm = (warp >> 2) * 64;
    int wn = (warp & 3) * 32;
    int r = lane >> 2;
    int c = lane & 3;

    const float* Ab = Ap + (size_t)bm * 128 * K;
    const float* Bb = Bm + (size_t)bn * 128;

    int aM = tid >> 1;
    int aK = (tid & 1) * 16;
    int bK = tid >> 3;
    int bN = (tid & 7) * 16;

    float acc[4][4][4];
    #pragma unroll
    for (int mi = 0; mi < 4; mi++)
        #pragma unroll
        for (int ni = 0; ni < 4; ni++)
            #pragma unroll
            for (int e = 0; e < 4; e++) acc[mi][ni][e] = 0.f;

    float4 aPref[4], bPref[4];
    #pragma unroll
    for (int j = 0; j < 4; j++) {
        aPref[j] = *(const float4*)(Ab + (size_t)aM * K + aK + j * 4);
        bPref[j] = *(const float4*)(Bb + (size_t)bK * N + bN + j * 4);
    }

    for (int k0 = 0; k0 < K; k0 += 32) {
        #pragma unroll
        for (int j = 0; j < 4; j++) {
            *(float4*)&As[aM][aK + j * 4] = aPref[j];
            *(float4*)&Bs[bK][bN + j * 4] = bPref[j];
        }
        __syncthreads();

        if (k0 + 32 < K) {
            #pragma unroll
            for (int j = 0; j < 4; j++) {
                aPref[j] = *(const float4*)(Ab + (size_t)aM * K + k0 + 32 + aK + j * 4);
                bPref[j] = *(const float4*)(Bb + (size_t)(k0 + 32 + bK) * N + bN + j * 4);
            }
        }

        #pragma unroll
        for (int ks = 0; ks < 4; ks++) {
            int k8 = ks * 8;
            uint32_t abig[4][4], asml[4][4];
            #pragma unroll
            for (int mi = 0; mi < 4; mi++) {
                int mrow = wm + mi * 16 + r;
                float a0 = As[mrow][k8 + c];
                float a1 = As[mrow + 8][k8 + c];
                float a2 = As[mrow][k8 + c + 4];
                float a3 = As[mrow + 8][k8 + c + 4];
                abig[mi][0] = f2tf32(a0); asml[mi][0] = f2tf32(a0 - __uint_as_float(abig[mi][0]));
                abig[mi][1] = f2tf32(a1); asml[mi][1] = f2tf32(a1 - __uint_as_float(abig[mi][1]));
                abig[mi][2] = f2tf32(a2); asml[mi][2] = f2tf32(a2 - __uint_as_float(abig[mi][2]));
                abig[mi][3] = f2tf32(a3); asml[mi][3] = f2tf32(a3 - __uint_as_float(abig[mi][3]));
            }
            uint32_t bbig[4][2], bsml[4][2];
            #pragma unroll
            for (int ni = 0; ni < 4; ni++) {
                int ncol = wn + ni * 8 + r;
                float b0 = Bs[k8 + c][ncol];
                float b1 = Bs[k8 + c + 4][ncol];
                bbig[ni][0] = f2tf32(b0); bsml[ni][0] = f2tf32(b0 - __uint_as_float(bbig[ni][0]));
                bbig[ni][1] = f2tf32(b1); bsml[ni][1] = f2tf32(b1 - __uint_as_float(bbig[ni][1]));
            }
            #pragma unroll
            for (int mi = 0; mi < 4; mi++)
                #pragma unroll
                for (int ni = 0; ni < 4; ni++) {
                    float* d = acc[mi][ni];
                    mma_tf32(d[0], d[1], d[2], d[3],
                             abig[mi][0], abig[mi][1], abig[mi][2], abig[mi][3],
                             bbig[ni][0], bbig[ni][1]);
                    mma_tf32(d[0], d[1], d[2], d[3],
                             abig[mi][0], abig[mi][1], abig[mi][2], abig[mi][3],
                             bsml[ni][0], bsml[ni][1]);
                    mma_tf32(d[0], d[1], d[2], d[3],
                             asml[mi][0], asml[mi][1], asml[mi][2], asml[mi][3],
                             bbig[ni][0], bbig[ni][1]);
                }
        }
        __syncthreads();
    }

    if (mode == 0) {
        float scale = 0.125f / (float)(lidx[0] + 1);
        #pragma unroll
        for (int mi = 0; mi < 4; mi++) {
            #pragma unroll
            for (int ni = 0; ni < 4; ni++) {
                #pragma unroll
                for (int e = 0; e < 4; e++) {
                    int m = bm * 128 + wm + mi * 16 + r + (e >> 1) * 8;
                    int n = bn * 128 + wn + ni * 8 + c * 2 + (e & 1);
                    float v = acc[mi][ni][e] + bias[n];
                    int b = m >> 11, s = m & 2047;
                    int t = n >> 10;
                    int hd = n & 1023;
                    int h = hd >> 6, d = hd & 63;
                    size_t idx = ((size_t)(b * HSZ + h) * SSZ + s) * DSZ + d;
                    if (t == 0)      g_q[idx] = v * scale;
                    else if (t == 1) g_k[idx] = v;
                    else             g_v[idx] = v;
                }
            }
        }
    } else {
        #pragma unroll
        for (int mi = 0; mi < 4; mi++) {
            #pragma unroll
            for (int ni = 0; ni < 4; ni++) {
                #pragma unroll
                for (int e = 0; e < 4; e++) {
                    int m = bm * 128 + wm + mi * 16 + r + (e >> 1) * 8;
                    int n = bn * 128 + wn + ni * 8 + c * 2 + (e & 1);
                    out[(size_t)m * N + n] = acc[mi][ni][e] + bias[n];
                }
            }
        }
    }
}

// ---------------------------------------------------------------------------
// Tensor-core flash attention. Block = 128 query rows of one (b,h).
// 8 warps x 16 rows. QK^T single-pass tf32; PV with 3-term tf32 compensation.
// Softmax fully in accumulator registers (quad shfl reductions).
// ---------------------------------------------------------------------------
__global__ __launch_bounds__(256, 1) void attn_tc_kernel()
{
    extern __shared__ float sm[];
    float (*Ks)[APAD] = (float(*)[APAD])sm;                         // [64][68]
    float (*Vs)[VPAD] = (float(*)[VPAD])(sm + 64 * APAD);           // [64][72]
    float (*Ps)[APAD] = (float(*)[APAD])(sm + 64 * APAD + 64 * VPAD); // [128][68]

    int bh = blockIdx.y;
    int qb = 15 - blockIdx.x;      // heavy (long-causal) blocks first
    int q0 = qb * 128;

    const float* qp = g_q + (size_t)bh * SSZ * DSZ + (size_t)q0 * DSZ;
    const float* kb = g_k + (size_t)bh * SSZ * DSZ;
    const float* vb = g_v + (size_t)bh * SSZ * DSZ;

    int tid = threadIdx.x, lane = tid & 31, warp = tid >> 5;
    int r = lane >> 2, c = lane & 3;
    int wr0 = warp * 16;

    // Phase 1: Q tile -> smem -> tf32 A-fragments in registers (held all kernel)
    {
        float (*Qs)[APAD] = (float(*)[APAD])sm;   // reuse smem
        for (int i = tid; i < 128 * 16; i += 256) {
            int row = i >> 4, col4 = (i & 15) * 4;
            *(float4*)&Qs[row][col4] = *(const float4*)(qp + row * 64 + col4);
        }
        __syncthreads();
    }
    uint32_t qa[8][4];
    {
        float (*Qs)[APAD] = (float(*)[APAD])sm;
        #pragma unroll
        for (int ks = 0; ks < 8; ks++) {
            int k8 = ks * 8;
            qa[ks][0] = f2tf32(Qs[wr0 + r][k8 + c]);
            qa[ks][1] = f2tf32(Qs[wr0 + r + 8][k8 + c]);
            qa[ks][2] = f2tf32(Qs[wr0 + r][k8 + c + 4]);
            qa[ks][3] = f2tf32(Qs[wr0 + r + 8][k8 + c + 4]);
        }
    }

    float m0 = -1e30f, m1 = -1e30f, l0 = 0.f, l1 = 0.f;
    float o[8][4];
    #pragma unroll
    for (int ni = 0; ni < 8; ni++)
        #pragma unroll
        for (int e = 0; e < 4; e++) o[ni][e] = 0.f;

    int qrow0 = q0 + wr0 + r;
    int qrow1 = qrow0 + 8;

    int ntiles = (qb + 1) * 2;
    for (int kt = 0; kt < ntiles; kt++) {
        __syncthreads();   // previous PV done before K/V overwrite (and Q phase)
        const float* kp = kb + (size_t)kt * 64 * DSZ;
        const float* vp = vb + (size_t)kt * 64 * DSZ;
        for (int i = tid; i < 1024; i += 256) {
            int row = i >> 4, col4 = (i & 15) * 4;
            *(float4*)&Ks[row][col4] = *(const float4*)(kp + row * 64 + col4);
            *(float4*)&Vs[row][col4] = *(const float4*)(vp + row * 64 + col4);
        }
        __syncthreads();

        // QK^T: scores in accumulator frags (single-pass tf32)
        float s[8][4];
        #pragma unroll
        for (int ni = 0; ni < 8; ni++)
            #pragma unroll
            for (int e = 0; e < 4; e++) s[ni][e] = 0.f;

        #pragma unroll
        for (int ks = 0; ks < 8; ks++) {
            int k8 = ks * 8;
            #pragma unroll
            for (int ni = 0; ni < 8; ni++) {
                uint32_t b0 = f2tf32(Ks[ni * 8 + r][k8 + c]);
                uint32_t b1 = f2tf32(Ks[ni * 8 + r][k8 + c + 4]);
                mma_tf32(s[ni][0], s[ni][1], s[ni][2], s[ni][3],
                         qa[ks][0], qa[ks][1], qa[ks][2], qa[ks][3], b0, b1);
            }
        }

        // causal mask
        if (kt * 64 + 63 > qrow0) {
            #pragma unroll
            for (int ni = 0; ni < 8; ni++) {
                int key = kt * 64 + ni * 8 + 2 * c;
                if (key     > qrow0) s[ni][0] = -1e30f;
                if (key + 1 > qrow0) s[ni][1] = -1e30f;
                if (key     > qrow1) s[ni][2] = -1e30f;
                if (key + 1 > qrow1) s[ni][3] = -1e30f;
            }
        }

        // row max (row r -> e0,e1; row r+8 -> e2,e3), reduce over quad (xor 1,2)
        float mx0 = -1e30f, mx1 = -1e30f;
        #pragma unroll
        for (int ni = 0; ni < 8; ni++) {
            mx0 = fmaxf(mx0, fmaxf(s[ni][0], s[ni][1]));
            mx1 = fmaxf(mx1, fmaxf(s[ni][2], s[ni][3]));
        }
        mx0 = fmaxf(mx0, __shfl_xor_sync(0xffffffffu, mx0, 1));
        mx0 = fmaxf(mx0, __shfl_xor_sync(0xffffffffu, mx0, 2));
        mx1 = fmaxf(mx1, __shfl_xor_sync(0xffffffffu, mx1, 1));
        mx1 = fmaxf(mx1, __shfl_xor_sync(0xffffffffu, mx1, 2));

        float mn0 = fmaxf(m0, mx0), mn1 = fmaxf(m1, mx1);
        float sum0 = 0.f, sum1 = 0.f;
        #pragma unroll
        for (int ni = 0; ni < 8; ni++) {
            float p0 = __expf(s[ni][0] - mn0);
            float p1 = __expf(s[ni][1] - mn0);
            float p2 = __expf(s[ni][2] - mn1);
            float p3 = __expf(s[ni][3] - mn1);
            sum0 += p0 + p1;
            sum1 += p2 + p3;
            *(float2*)&Ps[wr0 + r][ni * 8 + 2 * c]     = make_float2(p0, p1);
            *(float2*)&Ps[wr0 + r + 8][ni * 8 + 2 * c] = make_float2(p2, p3);
        }
        sum0 += __shfl_xor_sync(0xffffffffu, sum0, 1);
        sum0 += __shfl_xor_sync(0xffffffffu, sum0, 2);
        sum1 += __shfl_xor_sync(0xffffffffu, sum1, 1);
        sum1 += __shfl_xor_sync(0xffffffffu, sum1, 2);

        float alpha0 = __expf(m0 - mn0);
        float alpha1 = __expf(m1 - mn1);
        l0 = l0 * alpha0 + sum0;  m0 = mn0;
        l1 = l1 * alpha1 + sum1;  m1 = mn1;
        #pragma unroll
        for (int ni = 0; ni < 8; ni++) {
            o[ni][0] *= alpha0; o[ni][1] *= alpha0;
            o[ni][2] *= alpha1; o[ni][3] *= alpha1;
        }
        __syncwarp();   // Ps region is warp-private; warp-scope sync suffices

        // PV: O += P * V  (3-term tf32 compensation)
        #pragma unroll
        for (int ks = 0; ks < 8; ks++) {
            int k8 = ks * 8;
            float f0 = Ps[wr0 + r][k8 + c];
            float f1 = Ps[wr0 + r + 8][k8 + c];
            float f2 = Ps[wr0 + r][k8 + c + 4];
            float f3 = Ps[wr0 + r + 8][k8 + c + 4];
            uint32_t pb0 = f2tf32(f0), pb1 = f2tf32(f1), pb2 = f2tf32(f2), pb3 = f2tf32(f3);
            uint32_t ps0 = f2tf32(f0 - __uint_as_float(pb0));
            uint32_t ps1 = f2tf32(f1 - __uint_as_float(pb1));
            uint32_t ps2 = f2tf32(f2 - __uint_as_float(pb2));
            uint32_t ps3 = f2tf32(f3 - __uint_as_float(pb3));
            #pragma unroll
            for (int ni = 0; ni < 8; ni++) {
                float v0 = Vs[k8 + c][ni * 8 + r];
                float v1 = Vs[k8 + c + 4][ni * 8 + r];
                uint32_t vb0 = f2tf32(v0), vb1 = f2tf32(v1);
                uint32_t vs0 = f2tf32(v0 - __uint_as_float(vb0));
                uint32_t vs1 = f2tf32(v1 - __uint_as_float(vb1));
                mma_tf32(o[ni][0], o[ni][1], o[ni][2], o[ni][3],
                         pb0, pb1, pb2, pb3, vb0, vb1);
                mma_tf32(o[ni][0], o[ni][1], o[ni][2], o[ni][3],
                         ps0, ps1, ps2, ps3, vb0, vb1);
                mma_tf32(o[ni][0], o[ni][1], o[ni][2], o[ni][3],
                         pb0, pb1, pb2, pb3, vs0, vs1);
            }
        }
    }

    // Epilogue: normalize and write [B][S][H][D]
    int b = bh >> 4, h = bh & 15;
    float inv0 = 1.f / l0, inv1 = 1.f / l1;
    int s0 = q0 + wr0 + r, s1 = s0 + 8;
    size_t base0 = ((size_t)(b * SSZ + s0) * HSZ + h) * DSZ;
    size_t base1 = ((size_t)(b * SSZ + s1) * HSZ + h) * DSZ;
    #pragma unroll
    for (int ni = 0; ni < 8; ni++) {
        int d0 = ni * 8 + 2 * c;
        *(float2*)&g_attn[base0 + d0] = make_float2(o[ni][0] * inv0, o[ni][1] * inv0);
        *(float2*)&g_attn[base1 + d0] = make_float2(o[ni][2] * inv1, o[ni][3] * inv1);
    }
}

extern "C" void kernel_launch(void* const* d_in, const int* in_sizes, int n_in,
                              void* d_out, int out_size)
{
    const float* hidden = (const float*)d_in[0];
    const float* Wqkv  = (const float*)d_in[2];
    const float* bqkv  = (const float*)d_in[3];
    const float* Wproj = (const float*)d_in[4];
    const float* bproj = (const float*)d_in[5];
    const int*   lidx  = (const int*)d_in[6];
    float* out = (float*)d_out;

    int attn_smem = (64 * APAD + 64 * VPAD + 128 * APAD) * 4;
    cudaFuncSetAttribute(attn_tc_kernel,
        cudaFuncAttributeMaxDynamicSharedMemorySize, attn_smem);

    // QKV projection: M=8192, N=3072, K=1024
    gemm_tc_kernel<<<dim3(24, 64), 256>>>(hidden, Wqkv, bqkv, nullptr, lidx, 3072, 0);
    // Attention: 16 query tiles (128 rows each) x 64 (b,h) pairs
    attn_tc_kernel<<<dim3(16, 64), 256, attn_smem>>>();
    // Output projection: M=8192, N=1024, K=1024 (A := g_attn inside kernel)
    gemm_tc_kernel<<<dim3(8, 64), 256>>>(nullptr, Wproj, bproj, out, lidx, 1024, 1);
}